// round 5
// baseline (speedup 1.0000x reference)
#include <cuda_runtime.h>

// ---- static problem shape -------------------------------------------------
#define BATCH   8
#define HH      32
#define WWID    32
#define CDIM    768
#define NHEADS  12
#define HD      64
#define SEQ     1024
#define BHEADS  96
#define N_QKV   2304

// ---- scratch (device globals; allocation is forbidden) --------------------
__device__ float g_Q  [(size_t)BHEADS * SEQ * HD];
__device__ float g_K  [(size_t)BHEADS * SEQ * HD];
__device__ float g_V  [(size_t)BHEADS * SEQ * HD];
__device__ float g_RH [(size_t)BHEADS * SEQ * HH];
__device__ float g_RW [(size_t)BHEADS * SEQ * WWID];
__device__ float g_ATT[(size_t)BATCH * SEQ * CDIM];

// ---- helpers --------------------------------------------------------------
__device__ __forceinline__ unsigned f2tf(float f) {
    unsigned r;
    asm("cvt.rna.tf32.f32 %0, %1;" : "=r"(r) : "f"(f));
    return r;
}
__device__ __forceinline__ void mma_tf32(float c[4], const unsigned a[4],
                                         const unsigned b[2]) {
    asm volatile(
        "mma.sync.aligned.m16n8k8.row.col.f32.tf32.tf32.f32 "
        "{%0,%1,%2,%3},{%4,%5,%6,%7},{%8,%9},{%0,%1,%2,%3};"
        : "+f"(c[0]), "+f"(c[1]), "+f"(c[2]), "+f"(c[3])
        : "r"(a[0]), "r"(a[1]), "r"(a[2]), "r"(a[3]), "r"(b[0]), "r"(b[1]));
}
__device__ __forceinline__ unsigned s2u(const void* p) {
    return (unsigned)__cvta_generic_to_shared(p);
}
#define CP16(dst, src) \
    asm volatile("cp.async.cg.shared.global [%0], [%1], 16;" \
                 :: "r"(dst), "l"(src))
#define CPCOMMIT() asm volatile("cp.async.commit_group;")
#define CPWAIT(n)  asm volatile("cp.async.wait_group %0;" :: "n"(n))

// ===========================================================================
// tf32 GEMM, cp.async 4-stage pipeline, k-step 16.
// out(M x N) = X(M x 768) @ W(768 x N) + bias, computed transposed.
// Stage layout (words): Ws[16][136] (2176) | Xs[128][20] (2560) -> 4736/stage.
// Each thread converts in place exactly the 4 float4s it cp.async'd.
// ===========================================================================
template<int LDN, bool QKV_SCATTER>
__global__ void __launch_bounds__(256, 2) gemm_tf32_kernel(
    const float* __restrict__ X, const float* __restrict__ W,
    const float* __restrict__ bias, float* __restrict__ out)
{
    extern __shared__ unsigned smem[];   // 4 * 4736 words

    const int t = threadIdx.x;
    const int w = t >> 5, lane = t & 31, g = lane >> 2, t4 = lane & 3;
    const int warpN = (w & 3) * 32, warpM = (w >> 2) * 64;
    const int bn = blockIdx.x * 128, bm = blockIdx.y * 128;

    // per-thread copy coordinates
    const int wr0 = t >> 5;              // W rows: wr0 and wr0+8
    const int wc0 = (t & 31) * 4;        // W col
    const int xm0 = t >> 2;              // X rows: xm0 and xm0+64
    const int xk0 = (t & 3) * 4;         // X k-col

    auto issue = [&](int i_, int s_) {
        unsigned* st = smem + s_ * 4736;
        const int k0_ = i_ * 16;
        CP16(s2u(st + wr0 * 136 + wc0),
             W + (size_t)(k0_ + wr0) * LDN + bn + wc0);
        CP16(s2u(st + (wr0 + 8) * 136 + wc0),
             W + (size_t)(k0_ + wr0 + 8) * LDN + bn + wc0);
        unsigned* xt = st + 2176;
        CP16(s2u(xt + xm0 * 20 + xk0),
             X + (size_t)(bm + xm0) * CDIM + k0_ + xk0);
        CP16(s2u(xt + (xm0 + 64) * 20 + xk0),
             X + (size_t)(bm + xm0 + 64) * CDIM + k0_ + xk0);
        CPCOMMIT();
    };
    auto cvt16 = [&](unsigned* p) {
        float4 v = *(float4*)p;
        *(uint4*)p = make_uint4(f2tf(v.x), f2tf(v.y), f2tf(v.z), f2tf(v.w));
    };

    float acc[2][8][4] = {};

    issue(0, 0);
    issue(1, 1);

    for (int i = 0; i < 48; i++) {
        const int s = i & 3;
        CPWAIT(1);            // tile i (this thread's copies) complete
        __syncthreads();      // all threads' tile-i data visible; iter i-1 done
        if (i + 2 < 48) issue(i + 2, (i + 2) & 3);

        unsigned* st = smem + s * 4736;
        unsigned* xt = st + 2176;
        cvt16(st + wr0 * 136 + wc0);
        cvt16(st + (wr0 + 8) * 136 + wc0);
        cvt16(xt + xm0 * 20 + xk0);
        cvt16(xt + (xm0 + 64) * 20 + xk0);
        __syncthreads();      // converted tile visible to all

#pragma unroll
        for (int ks = 0; ks < 2; ks++) {
            const int kk = ks * 8 + t4;
            unsigned a[2][4];
#pragma unroll
            for (int mt = 0; mt < 2; mt++) {
                const int nb = warpN + mt * 16 + g;
                a[mt][0] = st[kk * 136 + nb];
                a[mt][1] = st[kk * 136 + nb + 8];
                a[mt][2] = st[(kk + 4) * 136 + nb];
                a[mt][3] = st[(kk + 4) * 136 + nb + 8];
            }
#pragma unroll
            for (int nt = 0; nt < 8; nt++) {
                unsigned b[2];
                const int mr = (warpM + nt * 8 + g) * 20 + kk;
                b[0] = xt[mr];
                b[1] = xt[mr + 4];
                mma_tf32(acc[0][nt], a[0], b);
                mma_tf32(acc[1][nt], a[1], b);
            }
        }
    }

#pragma unroll
    for (int mt = 0; mt < 2; mt++) {
#pragma unroll
        for (int nt = 0; nt < 8; nt++) {
            const int ncol0 = bn + warpN + mt * 16 + g;
            const int mrow  = bm + warpM + nt * 8 + 2 * t4;
#pragma unroll
            for (int h8 = 0; h8 < 2; h8++) {
                const int ncol = ncol0 + h8 * 8;
                const float bs = __ldg(bias + ncol);
                const float v0 = acc[mt][nt][h8 * 2 + 0] + bs;
                const float v1 = acc[mt][nt][h8 * 2 + 1] + bs;
                if (QKV_SCATTER) {
                    const int which = ncol / CDIM;
                    const int rem   = ncol - which * CDIM;
                    const int h = rem >> 6, d = rem & 63;
                    float* dst = (which == 0) ? g_Q : (which == 1) ? g_K : g_V;
                    const int b_ = mrow >> 10, s_ = mrow & 1023;
                    const size_t base =
                        ((size_t)(b_ * NHEADS + h) * SEQ + s_) * HD + d;
                    dst[base]      = v0;
                    dst[base + HD] = v1;
                } else {
                    out[(size_t)mrow * CDIM + ncol]       = v0;
                    out[(size_t)(mrow + 1) * CDIM + ncol] = v1;
                }
            }
        }
    }
}

// ===========================================================================
// relative-position bias tables (unchanged from round 4).
// ===========================================================================
__global__ void __launch_bounds__(256) rel_kernel(
    const float* __restrict__ rph, const float* __restrict__ rpw)
{
    __shared__ float Qs[32 * 65];
    __shared__ float Hs[32 * 65];
    __shared__ float Wt[63 * 65];

    const int bh = blockIdx.y;
    const int qh = blockIdx.x;
    const int t  = threadIdx.x;

    const float* Qg = g_Q + ((size_t)bh * SEQ + qh * 32) * HD;
#pragma unroll
    for (int i = t; i < 2048; i += 256) {
        const int r = i >> 6, d = i & 63;
        Qs[r * 65 + d] = Qg[i];
        Hs[r * 65 + d] = __ldg(rph + (qh + r) * 64 + d);
    }
    for (int i = t; i < 4032; i += 256) {
        const int r = i >> 6, d = i & 63;
        Wt[r * 65 + d] = __ldg(rpw + i);
    }
    __syncthreads();

    const int w = t >> 5, lane = t & 31;
    const float* Qr = Qs + lane * 65;
    float acc[8] = {};

    if (w < 4) {
        const int baserow = 31 - w * 8;
#pragma unroll
        for (int d = 0; d < 64; d++) {
            const float qv = Qr[d];
#pragma unroll
            for (int j = 0; j < 8; j++)
                acc[j] = fmaf(qv, Hs[(baserow - j) * 65 + d], acc[j]);
        }
        float* out = g_RH + ((size_t)bh * SEQ + qh * 32 + lane) * HH + w * 8;
        *(float4*)out       = make_float4(acc[0], acc[1], acc[2], acc[3]);
        *(float4*)(out + 4) = make_float4(acc[4], acc[5], acc[6], acc[7]);
    } else {
        const int baserow = lane + 31 - (w - 4) * 8;
#pragma unroll
        for (int d = 0; d < 64; d++) {
            const float qv = Qr[d];
#pragma unroll
            for (int j = 0; j < 8; j++)
                acc[j] = fmaf(qv, Wt[(baserow - j) * 65 + d], acc[j]);
        }
        float* out = g_RW + ((size_t)bh * SEQ + qh * 32 + lane) * WWID
                     + (w - 4) * 8;
        *(float4*)out       = make_float4(acc[0], acc[1], acc[2], acc[3]);
        *(float4*)(out + 4) = make_float4(acc[4], acc[5], acc[6], acc[7]);
    }
}

// ===========================================================================
// tf32 flash attention, cp.async 2-stage K/V pipeline.
// Stage layout (words): Ks[64][68] (4352) | Vs[64][72] (4608) -> 8960/stage.
// ===========================================================================
__global__ void __launch_bounds__(128, 3) flash_tf32_kernel()
{
    extern __shared__ unsigned fsm[];   // 2 * 8960 words

    const int t = threadIdx.x, w = t >> 5, lane = t & 31;
    const int g = lane >> 2, t4 = lane & 3;
    const int bh = blockIdx.y;
    const int q0 = blockIdx.x * 64;
    const int qrow = w * 16;
    const float scale = 0.125f;

    const float* Kg = g_K + (size_t)bh * SEQ * HD;
    const float* Vg = g_V + (size_t)bh * SEQ * HD;

    const int cr = t >> 4;          // base row for copies
    const int cc = (t & 15) * 4;    // col

    auto fissue = [&](int kt_, int s_) {
        unsigned* Kst = fsm + s_ * 8960;
        unsigned* Vst = Kst + 4352;
#pragma unroll
        for (int i = 0; i < 8; i++) {
            const int r = cr + 8 * i;
            CP16(s2u(Kst + r * 68 + cc),
                 Kg + (size_t)(kt_ * 64 + r) * HD + cc);
            CP16(s2u(Vst + r * 72 + cc),
                 Vg + (size_t)(kt_ * 64 + r) * HD + cc);
        }
        CPCOMMIT();
    };
    auto cvt16 = [&](unsigned* p) {
        float4 v = *(float4*)p;
        *(uint4*)p = make_uint4(f2tf(v.x), f2tf(v.y), f2tf(v.z), f2tf(v.w));
    };

    // ---- stage Q (scaled) through stage-0 K area, pull fragments ----------
    {
        const float* Qg = g_Q + ((size_t)bh * SEQ + q0) * HD;
#pragma unroll
        for (int i = 0; i < 8; i++) {
            const int r = cr + 8 * i;
            float4 v = *(const float4*)(Qg + r * HD + cc);
            *(uint4*)&fsm[r * 68 + cc] = make_uint4(
                f2tf(v.x * scale), f2tf(v.y * scale),
                f2tf(v.z * scale), f2tf(v.w * scale));
        }
        __syncthreads();
    }
    unsigned qa[8][4];
#pragma unroll
    for (int ks = 0; ks < 8; ks++) {
        const int kk = ks * 8 + t4;
        qa[ks][0] = fsm[(qrow + g) * 68 + kk];
        qa[ks][1] = fsm[(qrow + g + 8) * 68 + kk];
        qa[ks][2] = fsm[(qrow + g) * 68 + kk + 4];
        qa[ks][3] = fsm[(qrow + g + 8) * 68 + kk + 4];
    }
    __syncthreads();   // all Q frags read before tile 0 overwrites stage 0

    // ---- rw bias (tile-invariant) into registers --------------------------
    const float* RWg = g_RW + ((size_t)bh * SEQ + q0) * 32;
    float rwA[4][2], rwB[4][2];
#pragma unroll
    for (int nb = 0; nb < 4; nb++) {
        rwA[nb][0] = __ldg(RWg + (qrow + g) * 32 + nb * 8 + 2 * t4);
        rwA[nb][1] = __ldg(RWg + (qrow + g) * 32 + nb * 8 + 2 * t4 + 1);
        rwB[nb][0] = __ldg(RWg + (qrow + g + 8) * 32 + nb * 8 + 2 * t4);
        rwB[nb][1] = __ldg(RWg + (qrow + g + 8) * 32 + nb * 8 + 2 * t4 + 1);
    }
    const float* RHg = g_RH + ((size_t)bh * SEQ + q0) * 32;

    float o[8][4] = {};
    float l0 = 0.f, l1 = 0.f;
    const unsigned quadbase = lane & ~3u;
    const unsigned srcA = quadbase | (t4 >> 1);

    fissue(0, 0);

    for (int kt = 0; kt < 16; kt++) {
        const int s = kt & 1;
        unsigned* Kst = fsm + s * 8960;
        unsigned* Vst = Kst + 4352;

        CPWAIT(0);           // tile kt complete (this thread)
        __syncthreads();     // visible to all; prior mma done
        if (kt + 1 < 16) fissue(kt + 1, (kt + 1) & 1);

        // convert own 16 float4s in place
#pragma unroll
        for (int i = 0; i < 8; i++) {
            const int r = cr + 8 * i;
            cvt16(Kst + r * 68 + cc);
            cvt16(Vst + r * 72 + cc);
        }
        __syncthreads();

        // ---- S = Q @ K^T --------------------------------------------------
        float sreg[8][4] = {};
#pragma unroll
        for (int ks = 0; ks < 8; ks++) {
            const int kk = ks * 8 + t4;
#pragma unroll
            for (int nt = 0; nt < 8; nt++) {
                unsigned b[2];
                b[0] = Kst[(nt * 8 + g) * 68 + kk];
                b[1] = Kst[(nt * 8 + g) * 68 + kk + 4];
                mma_tf32(sreg[nt], qa[ks], b);
            }
        }

        // ---- bias + exp + frag convert + O += P @ V -----------------------
        const float rhA0 = __ldg(RHg + (qrow + g) * 32 + kt * 2);
        const float rhA1 = __ldg(RHg + (qrow + g) * 32 + kt * 2 + 1);
        const float rhB0 = __ldg(RHg + (qrow + g + 8) * 32 + kt * 2);
        const float rhB1 = __ldg(RHg + (qrow + g + 8) * 32 + kt * 2 + 1);
#pragma unroll
        for (int nt = 0; nt < 8; nt++) {
            const float bA = (nt < 4) ? rhA0 : rhA1;
            const float bB = (nt < 4) ? rhB0 : rhB1;
            const int n4 = nt & 3;
            const float p00 = __expf(fminf(sreg[nt][0] + bA + rwA[n4][0], 60.f));
            const float p01 = __expf(fminf(sreg[nt][1] + bA + rwA[n4][1], 60.f));
            const float p10 = __expf(fminf(sreg[nt][2] + bB + rwB[n4][0], 60.f));
            const float p11 = __expf(fminf(sreg[nt][3] + bB + rwB[n4][1], 60.f));
            l0 += p00 + p01;
            l1 += p10 + p11;

            const bool oddsel = (t4 & 1);
            float xa, xb, ya, yb;
            xa = __shfl_sync(0xffffffffu, p00, srcA);
            xb = __shfl_sync(0xffffffffu, p01, srcA);
            const float loA = oddsel ? xb : xa;
            ya = __shfl_sync(0xffffffffu, p00, srcA + 2);
            yb = __shfl_sync(0xffffffffu, p01, srcA + 2);
            const float hiA = oddsel ? yb : ya;
            xa = __shfl_sync(0xffffffffu, p10, srcA);
            xb = __shfl_sync(0xffffffffu, p11, srcA);
            const float loB = oddsel ? xb : xa;
            ya = __shfl_sync(0xffffffffu, p10, srcA + 2);
            yb = __shfl_sync(0xffffffffu, p11, srcA + 2);
            const float hiB = oddsel ? yb : ya;

            unsigned ap[4];
            ap[0] = f2tf(loA);
            ap[1] = f2tf(loB);
            ap[2] = f2tf(hiA);
            ap[3] = f2tf(hiB);

            const int kc = nt * 8;
#pragma unroll
            for (int db = 0; db < 8; db++) {
                unsigned b[2];
                b[0] = Vst[(kc + t4) * 72 + db * 8 + g];
                b[1] = Vst[(kc + t4 + 4) * 72 + db * 8 + g];
                mma_tf32(o[db], ap, b);
            }
        }
    }

    l0 += __shfl_xor_sync(0xffffffffu, l0, 1);
    l0 += __shfl_xor_sync(0xffffffffu, l0, 2);
    l1 += __shfl_xor_sync(0xffffffffu, l1, 1);
    l1 += __shfl_xor_sync(0xffffffffu, l1, 2);
    const float inv0 = 1.f / l0;
    const float inv1 = 1.f / l1;

    const int b_ = bh / NHEADS, h = bh - b_ * NHEADS;
    const int rowA = q0 + qrow + g, rowB = rowA + 8;
    float* OgA = g_ATT + ((size_t)b_ * SEQ + rowA) * CDIM + h * HD;
    float* OgB = g_ATT + ((size_t)b_ * SEQ + rowB) * CDIM + h * HD;
#pragma unroll
    for (int db = 0; db < 8; db++) {
        const int c = db * 8 + 2 * t4;
        float2 vA = make_float2(o[db][0] * inv0, o[db][1] * inv0);
        float2 vB = make_float2(o[db][2] * inv1, o[db][3] * inv1);
        *(float2*)(OgA + c) = vA;
        *(float2*)(OgB + c) = vB;
    }
}

// ===========================================================================
// launch
// ===========================================================================
#define GEMM_SMEM (4 * 4736 * 4)
#define FLASH_SMEM (2 * 8960 * 4)

extern "C" void kernel_launch(void* const* d_in, const int* in_sizes, int n_in,
                              void* d_out, int out_size)
{
    const float* hidden = (const float*)d_in[0];
    const float* qkv_w  = (const float*)d_in[1];
    const float* qkv_b  = (const float*)d_in[2];
    const float* proj_w = (const float*)d_in[3];
    const float* proj_b = (const float*)d_in[4];
    const float* rph    = (const float*)d_in[5];
    const float* rpw    = (const float*)d_in[6];
    float* out = (float*)d_out;

    static bool init = false;
    if (!init) {
        cudaFuncSetAttribute(gemm_tf32_kernel<N_QKV, true>,
                             cudaFuncAttributeMaxDynamicSharedMemorySize,
                             GEMM_SMEM);
        cudaFuncSetAttribute(gemm_tf32_kernel<CDIM, false>,
                             cudaFuncAttributeMaxDynamicSharedMemorySize,
                             GEMM_SMEM);
        cudaFuncSetAttribute(flash_tf32_kernel,
                             cudaFuncAttributeMaxDynamicSharedMemorySize,
                             FLASH_SMEM);
        init = true;
    }

    float* att_ptr = nullptr;
    cudaGetSymbolAddress((void**)&att_ptr, g_ATT);

    gemm_tf32_kernel<N_QKV, true>
        <<<dim3(N_QKV / 128, (BATCH * SEQ) / 128), 256, GEMM_SMEM>>>(
            hidden, qkv_w, qkv_b, nullptr);
    rel_kernel<<<dim3(HH, BHEADS), 256>>>(rph, rpw);
    flash_tf32_kernel<<<dim3(SEQ / 64, BHEADS), 128, FLASH_SMEM>>>();
    gemm_tf32_kernel<CDIM, false>
        <<<dim3(CDIM / 128, (BATCH * SEQ) / 128), 256, GEMM_SMEM>>>(
            att_ptr, proj_w, proj_b, out);
}

// round 6
// speedup vs baseline: 1.0554x; 1.0554x over previous
#include <cuda_runtime.h>

// ---- static problem shape -------------------------------------------------
#define BATCH   8
#define HH      32
#define WWID    32
#define CDIM    768
#define NHEADS  12
#define HD      64
#define SEQ     1024
#define BHEADS  96
#define N_QKV   2304

// ---- scratch (device globals; allocation is forbidden) --------------------
__device__ float g_Q  [(size_t)BHEADS * SEQ * HD];
__device__ float g_K  [(size_t)BHEADS * SEQ * HD];
__device__ float g_V  [(size_t)BHEADS * SEQ * HD];
__device__ float g_RH [(size_t)BHEADS * SEQ * HH];
__device__ float g_RW [(size_t)BHEADS * SEQ * WWID];
__device__ float g_ATT[(size_t)BATCH * SEQ * CDIM];

// ---- helpers --------------------------------------------------------------
__device__ __forceinline__ unsigned f2tf(float f) {
    unsigned r;
    asm("cvt.rna.tf32.f32 %0, %1;" : "=r"(r) : "f"(f));
    return r;
}
__device__ __forceinline__ void mma_tf32(float c[4], const unsigned a[4],
                                         const unsigned b[2]) {
    asm volatile(
        "mma.sync.aligned.m16n8k8.row.col.f32.tf32.tf32.f32 "
        "{%0,%1,%2,%3},{%4,%5,%6,%7},{%8,%9},{%0,%1,%2,%3};"
        : "+f"(c[0]), "+f"(c[1]), "+f"(c[2]), "+f"(c[3])
        : "r"(a[0]), "r"(a[1]), "r"(a[2]), "r"(a[3]), "r"(b[0]), "r"(b[1]));
}
__device__ __forceinline__ unsigned s2u(const void* p) {
    return (unsigned)__cvta_generic_to_shared(p);
}
#define CP16(dst, src) \
    asm volatile("cp.async.cg.shared.global [%0], [%1], 16;" \
                 :: "r"(dst), "l"(src))
#define CPCOMMIT() asm volatile("cp.async.commit_group;")
#define CPWAIT(n)  asm volatile("cp.async.wait_group %0;" :: "n"(n))

// ===========================================================================
// tf32 GEMM, cp.async 2-stage pipeline, k-step 32 (round-4 compute structure).
// out(M x N) = X(M x 768) @ W(768 x N) + bias, computed transposed.
// Stage layout (words): Ws[32][136] (4352) | Xs[128][36] (4608) -> 8960/stage.
// Each thread converts in place exactly the 8 float4s it cp.async'd.
// ===========================================================================
template<int LDN, bool QKV_SCATTER>
__global__ void __launch_bounds__(256, 2) gemm_tf32_kernel(
    const float* __restrict__ X, const float* __restrict__ W,
    const float* __restrict__ bias, float* __restrict__ out)
{
    extern __shared__ unsigned smem[];   // 2 * 8960 words

    const int t = threadIdx.x;
    const int w = t >> 5, lane = t & 31, g = lane >> 2, t4 = lane & 3;
    const int warpN = (w & 3) * 32, warpM = (w >> 2) * 64;
    const int bn = blockIdx.x * 128, bm = blockIdx.y * 128;

    auto issue = [&](int i_, int s_) {
        unsigned* st = smem + s_ * 8960;
        unsigned* xt = st + 4352;
        const int k0_ = i_ * 32;
#pragma unroll
        for (int j = 0; j < 4; j++) {
            const int idx = t + 256 * j;
            const int wr = idx >> 5, wc = (idx & 31) * 4;
            CP16(s2u(st + wr * 136 + wc),
                 W + (size_t)(k0_ + wr) * LDN + bn + wc);
            const int xm = idx >> 3, xk = (idx & 7) * 4;
            CP16(s2u(xt + xm * 36 + xk),
                 X + (size_t)(bm + xm) * CDIM + k0_ + xk);
        }
        CPCOMMIT();
    };
    auto cvt16 = [&](unsigned* p) {
        float4 v = *(float4*)p;
        *(uint4*)p = make_uint4(f2tf(v.x), f2tf(v.y), f2tf(v.z), f2tf(v.w));
    };

    float acc[2][8][4] = {};

    issue(0, 0);

    for (int i = 0; i < 24; i++) {
        const int s = i & 1;
        unsigned* st = smem + s * 8960;
        unsigned* xt = st + 4352;

        CPWAIT(0);            // tile i complete (this thread's copies)
        __syncthreads();      // visible to all; compute of i-1 done
        if (i + 1 < 24) issue(i + 1, s ^ 1);

#pragma unroll
        for (int j = 0; j < 4; j++) {
            const int idx = t + 256 * j;
            cvt16(st + (idx >> 5) * 136 + (idx & 31) * 4);
            cvt16(xt + (idx >> 3) * 36 + (idx & 7) * 4);
        }
        __syncthreads();      // converted tile visible

#pragma unroll
        for (int ks = 0; ks < 4; ks++) {
            const int kk = ks * 8 + t4;
            unsigned a[2][4];
#pragma unroll
            for (int mt = 0; mt < 2; mt++) {
                const int nb = warpN + mt * 16 + g;
                a[mt][0] = st[kk * 136 + nb];
                a[mt][1] = st[kk * 136 + nb + 8];
                a[mt][2] = st[(kk + 4) * 136 + nb];
                a[mt][3] = st[(kk + 4) * 136 + nb + 8];
            }
#pragma unroll
            for (int nt = 0; nt < 8; nt++) {
                unsigned b[2];
                const int mr = (warpM + nt * 8 + g) * 36 + kk;
                b[0] = xt[mr];
                b[1] = xt[mr + 4];
                mma_tf32(acc[0][nt], a[0], b);
                mma_tf32(acc[1][nt], a[1], b);
            }
        }
    }

#pragma unroll
    for (int mt = 0; mt < 2; mt++) {
#pragma unroll
        for (int nt = 0; nt < 8; nt++) {
            const int ncol0 = bn + warpN + mt * 16 + g;
            const int mrow  = bm + warpM + nt * 8 + 2 * t4;
#pragma unroll
            for (int h8 = 0; h8 < 2; h8++) {
                const int ncol = ncol0 + h8 * 8;
                const float bs = __ldg(bias + ncol);
                const float v0 = acc[mt][nt][h8 * 2 + 0] + bs;
                const float v1 = acc[mt][nt][h8 * 2 + 1] + bs;
                if (QKV_SCATTER) {
                    const int which = ncol / CDIM;
                    const int rem   = ncol - which * CDIM;
                    const int h = rem >> 6, d = rem & 63;
                    float* dst = (which == 0) ? g_Q : (which == 1) ? g_K : g_V;
                    const int b_ = mrow >> 10, s_ = mrow & 1023;
                    const size_t base =
                        ((size_t)(b_ * NHEADS + h) * SEQ + s_) * HD + d;
                    dst[base]      = v0;
                    dst[base + HD] = v1;
                } else {
                    out[(size_t)mrow * CDIM + ncol]       = v0;
                    out[(size_t)(mrow + 1) * CDIM + ncol] = v1;
                }
            }
        }
    }
}

// ===========================================================================
// relative-position bias tables (unchanged).
// ===========================================================================
__global__ void __launch_bounds__(256) rel_kernel(
    const float* __restrict__ rph, const float* __restrict__ rpw)
{
    __shared__ float Qs[32 * 65];
    __shared__ float Hs[32 * 65];
    __shared__ float Wt[63 * 65];

    const int bh = blockIdx.y;
    const int qh = blockIdx.x;
    const int t  = threadIdx.x;

    const float* Qg = g_Q + ((size_t)bh * SEQ + qh * 32) * HD;
#pragma unroll
    for (int i = t; i < 2048; i += 256) {
        const int r = i >> 6, d = i & 63;
        Qs[r * 65 + d] = Qg[i];
        Hs[r * 65 + d] = __ldg(rph + (qh + r) * 64 + d);
    }
    for (int i = t; i < 4032; i += 256) {
        const int r = i >> 6, d = i & 63;
        Wt[r * 65 + d] = __ldg(rpw + i);
    }
    __syncthreads();

    const int w = t >> 5, lane = t & 31;
    const float* Qr = Qs + lane * 65;
    float acc[8] = {};

    if (w < 4) {
        const int baserow = 31 - w * 8;
#pragma unroll
        for (int d = 0; d < 64; d++) {
            const float qv = Qr[d];
#pragma unroll
            for (int j = 0; j < 8; j++)
                acc[j] = fmaf(qv, Hs[(baserow - j) * 65 + d], acc[j]);
        }
        float* out = g_RH + ((size_t)bh * SEQ + qh * 32 + lane) * HH + w * 8;
        *(float4*)out       = make_float4(acc[0], acc[1], acc[2], acc[3]);
        *(float4*)(out + 4) = make_float4(acc[4], acc[5], acc[6], acc[7]);
    } else {
        const int baserow = lane + 31 - (w - 4) * 8;
#pragma unroll
        for (int d = 0; d < 64; d++) {
            const float qv = Qr[d];
#pragma unroll
            for (int j = 0; j < 8; j++)
                acc[j] = fmaf(qv, Wt[(baserow - j) * 65 + d], acc[j]);
        }
        float* out = g_RW + ((size_t)bh * SEQ + qh * 32 + lane) * WWID
                     + (w - 4) * 8;
        *(float4*)out       = make_float4(acc[0], acc[1], acc[2], acc[3]);
        *(float4*)(out + 4) = make_float4(acc[4], acc[5], acc[6], acc[7]);
    }
}

// ===========================================================================
// tf32 flash attention, cp.async 2-stage K/V pipeline (unchanged structure).
// ===========================================================================
__global__ void __launch_bounds__(128, 3) flash_tf32_kernel()
{
    extern __shared__ unsigned fsm[];   // 2 * 8960 words

    const int t = threadIdx.x, w = t >> 5, lane = t & 31;
    const int g = lane >> 2, t4 = lane & 3;
    const int bh = blockIdx.y;
    const int q0 = blockIdx.x * 64;
    const int qrow = w * 16;
    const float scale = 0.125f;

    const float* Kg = g_K + (size_t)bh * SEQ * HD;
    const float* Vg = g_V + (size_t)bh * SEQ * HD;

    const int cr = t >> 4;
    const int cc = (t & 15) * 4;

    auto fissue = [&](int kt_, int s_) {
        unsigned* Kst = fsm + s_ * 8960;
        unsigned* Vst = Kst + 4352;
#pragma unroll
        for (int i = 0; i < 8; i++) {
            const int r = cr + 8 * i;
            CP16(s2u(Kst + r * 68 + cc),
                 Kg + (size_t)(kt_ * 64 + r) * HD + cc);
            CP16(s2u(Vst + r * 72 + cc),
                 Vg + (size_t)(kt_ * 64 + r) * HD + cc);
        }
        CPCOMMIT();
    };
    auto cvt16 = [&](unsigned* p) {
        float4 v = *(float4*)p;
        *(uint4*)p = make_uint4(f2tf(v.x), f2tf(v.y), f2tf(v.z), f2tf(v.w));
    };

    {
        const float* Qg = g_Q + ((size_t)bh * SEQ + q0) * HD;
#pragma unroll
        for (int i = 0; i < 8; i++) {
            const int r = cr + 8 * i;
            float4 v = *(const float4*)(Qg + r * HD + cc);
            *(uint4*)&fsm[r * 68 + cc] = make_uint4(
                f2tf(v.x * scale), f2tf(v.y * scale),
                f2tf(v.z * scale), f2tf(v.w * scale));
        }
        __syncthreads();
    }
    unsigned qa[8][4];
#pragma unroll
    for (int ks = 0; ks < 8; ks++) {
        const int kk = ks * 8 + t4;
        qa[ks][0] = fsm[(qrow + g) * 68 + kk];
        qa[ks][1] = fsm[(qrow + g + 8) * 68 + kk];
        qa[ks][2] = fsm[(qrow + g) * 68 + kk + 4];
        qa[ks][3] = fsm[(qrow + g + 8) * 68 + kk + 4];
    }
    __syncthreads();

    const float* RWg = g_RW + ((size_t)bh * SEQ + q0) * 32;
    float rwA[4][2], rwB[4][2];
#pragma unroll
    for (int nb = 0; nb < 4; nb++) {
        rwA[nb][0] = __ldg(RWg + (qrow + g) * 32 + nb * 8 + 2 * t4);
        rwA[nb][1] = __ldg(RWg + (qrow + g) * 32 + nb * 8 + 2 * t4 + 1);
        rwB[nb][0] = __ldg(RWg + (qrow + g + 8) * 32 + nb * 8 + 2 * t4);
        rwB[nb][1] = __ldg(RWg + (qrow + g + 8) * 32 + nb * 8 + 2 * t4 + 1);
    }
    const float* RHg = g_RH + ((size_t)bh * SEQ + q0) * 32;

    float o[8][4] = {};
    float l0 = 0.f, l1 = 0.f;
    const unsigned quadbase = lane & ~3u;
    const unsigned srcA = quadbase | (t4 >> 1);

    fissue(0, 0);

    for (int kt = 0; kt < 16; kt++) {
        const int s = kt & 1;
        unsigned* Kst = fsm + s * 8960;
        unsigned* Vst = Kst + 4352;

        CPWAIT(0);
        __syncthreads();
        if (kt + 1 < 16) fissue(kt + 1, s ^ 1);

#pragma unroll
        for (int i = 0; i < 8; i++) {
            const int r = cr + 8 * i;
            cvt16(Kst + r * 68 + cc);
            cvt16(Vst + r * 72 + cc);
        }
        __syncthreads();

        float sreg[8][4] = {};
#pragma unroll
        for (int ks = 0; ks < 8; ks++) {
            const int kk = ks * 8 + t4;
#pragma unroll
            for (int nt = 0; nt < 8; nt++) {
                unsigned b[2];
                b[0] = Kst[(nt * 8 + g) * 68 + kk];
                b[1] = Kst[(nt * 8 + g) * 68 + kk + 4];
                mma_tf32(sreg[nt], qa[ks], b);
            }
        }

        const float rhA0 = __ldg(RHg + (qrow + g) * 32 + kt * 2);
        const float rhA1 = __ldg(RHg + (qrow + g) * 32 + kt * 2 + 1);
        const float rhB0 = __ldg(RHg + (qrow + g + 8) * 32 + kt * 2);
        const float rhB1 = __ldg(RHg + (qrow + g + 8) * 32 + kt * 2 + 1);
#pragma unroll
        for (int nt = 0; nt < 8; nt++) {
            const float bA = (nt < 4) ? rhA0 : rhA1;
            const float bB = (nt < 4) ? rhB0 : rhB1;
            const int n4 = nt & 3;
            const float p00 = __expf(fminf(sreg[nt][0] + bA + rwA[n4][0], 60.f));
            const float p01 = __expf(fminf(sreg[nt][1] + bA + rwA[n4][1], 60.f));
            const float p10 = __expf(fminf(sreg[nt][2] + bB + rwB[n4][0], 60.f));
            const float p11 = __expf(fminf(sreg[nt][3] + bB + rwB[n4][1], 60.f));
            l0 += p00 + p01;
            l1 += p10 + p11;

            const bool oddsel = (t4 & 1);
            float xa, xb, ya, yb;
            xa = __shfl_sync(0xffffffffu, p00, srcA);
            xb = __shfl_sync(0xffffffffu, p01, srcA);
            const float loA = oddsel ? xb : xa;
            ya = __shfl_sync(0xffffffffu, p00, srcA + 2);
            yb = __shfl_sync(0xffffffffu, p01, srcA + 2);
            const float hiA = oddsel ? yb : ya;
            xa = __shfl_sync(0xffffffffu, p10, srcA);
            xb = __shfl_sync(0xffffffffu, p11, srcA);
            const float loB = oddsel ? xb : xa;
            ya = __shfl_sync(0xffffffffu, p10, srcA + 2);
            yb = __shfl_sync(0xffffffffu, p11, srcA + 2);
            const float hiB = oddsel ? yb : ya;

            unsigned ap[4];
            ap[0] = f2tf(loA);
            ap[1] = f2tf(loB);
            ap[2] = f2tf(hiA);
            ap[3] = f2tf(hiB);

            const int kc = nt * 8;
#pragma unroll
            for (int db = 0; db < 8; db++) {
                unsigned b[2];
                b[0] = Vst[(kc + t4) * 72 + db * 8 + g];
                b[1] = Vst[(kc + t4 + 4) * 72 + db * 8 + g];
                mma_tf32(o[db], ap, b);
            }
        }
    }

    l0 += __shfl_xor_sync(0xffffffffu, l0, 1);
    l0 += __shfl_xor_sync(0xffffffffu, l0, 2);
    l1 += __shfl_xor_sync(0xffffffffu, l1, 1);
    l1 += __shfl_xor_sync(0xffffffffu, l1, 2);
    const float inv0 = 1.f / l0;
    const float inv1 = 1.f / l1;

    const int b_ = bh / NHEADS, h = bh - b_ * NHEADS;
    const int rowA = q0 + qrow + g, rowB = rowA + 8;
    float* OgA = g_ATT + ((size_t)b_ * SEQ + rowA) * CDIM + h * HD;
    float* OgB = g_ATT + ((size_t)b_ * SEQ + rowB) * CDIM + h * HD;
#pragma unroll
    for (int db = 0; db < 8; db++) {
        const int c = db * 8 + 2 * t4;
        float2 vA = make_float2(o[db][0] * inv0, o[db][1] * inv0);
        float2 vB = make_float2(o[db][2] * inv1, o[db][3] * inv1);
        *(float2*)(OgA + c) = vA;
        *(float2*)(OgB + c) = vB;
    }
}

// ===========================================================================
// launch
// ===========================================================================
#define GEMM_SMEM (2 * 8960 * 4)
#define FLASH_SMEM (2 * 8960 * 4)

extern "C" void kernel_launch(void* const* d_in, const int* in_sizes, int n_in,
                              void* d_out, int out_size)
{
    const float* hidden = (const float*)d_in[0];
    const float* qkv_w  = (const float*)d_in[1];
    const float* qkv_b  = (const float*)d_in[2];
    const float* proj_w = (const float*)d_in[3];
    const float* proj_b = (const float*)d_in[4];
    const float* rph    = (const float*)d_in[5];
    const float* rpw    = (const float*)d_in[6];
    float* out = (float*)d_out;

    static bool init = false;
    if (!init) {
        cudaFuncSetAttribute(gemm_tf32_kernel<N_QKV, true>,
                             cudaFuncAttributeMaxDynamicSharedMemorySize,
                             GEMM_SMEM);
        cudaFuncSetAttribute(gemm_tf32_kernel<CDIM, false>,
                             cudaFuncAttributeMaxDynamicSharedMemorySize,
                             GEMM_SMEM);
        cudaFuncSetAttribute(flash_tf32_kernel,
                             cudaFuncAttributeMaxDynamicSharedMemorySize,
                             FLASH_SMEM);
        init = true;
    }

    float* att_ptr = nullptr;
    cudaGetSymbolAddress((void**)&att_ptr, g_ATT);

    gemm_tf32_kernel<N_QKV, true>
        <<<dim3(N_QKV / 128, (BATCH * SEQ) / 128), 256, GEMM_SMEM>>>(
            hidden, qkv_w, qkv_b, nullptr);
    rel_kernel<<<dim3(HH, BHEADS), 256>>>(rph, rpw);
    flash_tf32_kernel<<<dim3(SEQ / 64, BHEADS), 128, FLASH_SMEM>>>();
    gemm_tf32_kernel<CDIM, false>
        <<<dim3(CDIM / 128, (BATCH * SEQ) / 128), 256, GEMM_SMEM>>>(
            att_ptr, proj_w, proj_b, out);
}

// round 7
// speedup vs baseline: 1.2827x; 1.2154x over previous
#include <cuda_runtime.h>

// ---- static problem shape -------------------------------------------------
#define BATCH   8
#define HH      32
#define WWID    32
#define CDIM    768
#define NHEADS  12
#define HD      64
#define SEQ     1024
#define BHEADS  96
#define N_QKV   2304

// ---- scratch (device globals; allocation is forbidden) --------------------
// g_Q/g_K/g_V/g_ATT hold tf32 bit patterns (valid fp32 values).
__device__ float    g_Q  [(size_t)BHEADS * SEQ * HD];
__device__ float    g_K  [(size_t)BHEADS * SEQ * HD];
__device__ float    g_V  [(size_t)BHEADS * SEQ * HD];
__device__ float    g_RH [(size_t)BHEADS * SEQ * HH];
__device__ float    g_RW [(size_t)BHEADS * SEQ * WWID];
__device__ unsigned g_ATT[(size_t)BATCH * SEQ * CDIM];
__device__ unsigned g_X  [(size_t)BATCH * SEQ * CDIM];   // hidden, tf32
__device__ unsigned g_W1 [(size_t)CDIM * N_QKV];         // qkv_w, tf32
__device__ unsigned g_W2 [(size_t)CDIM * CDIM];          // proj_w, tf32

// ---- helpers --------------------------------------------------------------
__device__ __forceinline__ unsigned f2tf(float f) {
    unsigned r;
    asm("cvt.rna.tf32.f32 %0, %1;" : "=r"(r) : "f"(f));
    return r;
}
__device__ __forceinline__ void mma_tf32(float c[4], const unsigned a[4],
                                         const unsigned b[2]) {
    asm volatile(
        "mma.sync.aligned.m16n8k8.row.col.f32.tf32.tf32.f32 "
        "{%0,%1,%2,%3},{%4,%5,%6,%7},{%8,%9},{%0,%1,%2,%3};"
        : "+f"(c[0]), "+f"(c[1]), "+f"(c[2]), "+f"(c[3])
        : "r"(a[0]), "r"(a[1]), "r"(a[2]), "r"(a[3]), "r"(b[0]), "r"(b[1]));
}
__device__ __forceinline__ unsigned s2u(const void* p) {
    return (unsigned)__cvta_generic_to_shared(p);
}
#define CP16(dst, src) \
    asm volatile("cp.async.cg.shared.global [%0], [%1], 16;" \
                 :: "r"(dst), "l"(src))
#define CPCOMMIT() asm volatile("cp.async.commit_group;")
#define CPWAIT(n)  asm volatile("cp.async.wait_group %0;" :: "n"(n))

// ===========================================================================
// Pre-pass: fp32 -> tf32 (rna) elementwise, vectorized.
// ===========================================================================
__global__ void __launch_bounds__(256) cvt_kernel(
    const float4* __restrict__ src, uint4* __restrict__ dst, int n4)
{
    const int i = blockIdx.x * 256 + threadIdx.x;
    if (i < n4) {
        float4 v = src[i];
        dst[i] = make_uint4(f2tf(v.x), f2tf(v.y), f2tf(v.z), f2tf(v.w));
    }
}

// ===========================================================================
// tf32 GEMM, cp.async 2-stage, k-step 32, inputs already tf32 in global.
// out(M x N) = X(M x 768) @ W(768 x N) + bias, computed transposed.
// Stage layout (words): Ws[32][136] (4352) | Xs[128][36] (4608) -> 8960/stage.
// ONE barrier per tile; no conversion in the hot loop.
// ===========================================================================
template<int LDN, bool QKV_SCATTER>
__global__ void __launch_bounds__(256, 2) gemm_tf32_kernel(
    const unsigned* __restrict__ X, const unsigned* __restrict__ W,
    const float* __restrict__ bias, float* __restrict__ out)
{
    extern __shared__ unsigned smem[];   // 2 * 8960 words

    const int t = threadIdx.x;
    const int w = t >> 5, lane = t & 31, g = lane >> 2, t4 = lane & 3;
    const int warpN = (w & 3) * 32, warpM = (w >> 2) * 64;
    const int bn = blockIdx.x * 128, bm = blockIdx.y * 128;

    auto issue = [&](int i_, int s_) {
        unsigned* st = smem + s_ * 8960;
        unsigned* xt = st + 4352;
        const int k0_ = i_ * 32;
#pragma unroll
        for (int j = 0; j < 4; j++) {
            const int idx = t + 256 * j;
            const int wr = idx >> 5, wc = (idx & 31) * 4;
            CP16(s2u(st + wr * 136 + wc),
                 W + (size_t)(k0_ + wr) * LDN + bn + wc);
            const int xm = idx >> 3, xk = (idx & 7) * 4;
            CP16(s2u(xt + xm * 36 + xk),
                 X + (size_t)(bm + xm) * CDIM + k0_ + xk);
        }
        CPCOMMIT();
    };

    float acc[2][8][4] = {};

    issue(0, 0);

    for (int i = 0; i < 24; i++) {
        const int s = i & 1;
        unsigned* st = smem + s * 8960;
        unsigned* xt = st + 4352;

        CPWAIT(0);            // tile i complete (this thread's copies)
        __syncthreads();      // visible to all; compute of i-1 done everywhere
        if (i + 1 < 24) issue(i + 1, s ^ 1);

#pragma unroll
        for (int ks = 0; ks < 4; ks++) {
            const int kk = ks * 8 + t4;
            unsigned a[2][4];
#pragma unroll
            for (int mt = 0; mt < 2; mt++) {
                const int nb = warpN + mt * 16 + g;
                a[mt][0] = st[kk * 136 + nb];
                a[mt][1] = st[kk * 136 + nb + 8];
                a[mt][2] = st[(kk + 4) * 136 + nb];
                a[mt][3] = st[(kk + 4) * 136 + nb + 8];
            }
#pragma unroll
            for (int nt = 0; nt < 8; nt++) {
                unsigned b[2];
                const int mr = (warpM + nt * 8 + g) * 36 + kk;
                b[0] = xt[mr];
                b[1] = xt[mr + 4];
                mma_tf32(acc[0][nt], a[0], b);
                mma_tf32(acc[1][nt], a[1], b);
            }
        }
    }

#pragma unroll
    for (int mt = 0; mt < 2; mt++) {
#pragma unroll
        for (int nt = 0; nt < 8; nt++) {
            const int ncol0 = bn + warpN + mt * 16 + g;
            const int mrow  = bm + warpM + nt * 8 + 2 * t4;
#pragma unroll
            for (int h8 = 0; h8 < 2; h8++) {
                const int ncol = ncol0 + h8 * 8;
                const float bs = __ldg(bias + ncol);
                const float v0 = acc[mt][nt][h8 * 2 + 0] + bs;
                const float v1 = acc[mt][nt][h8 * 2 + 1] + bs;
                if (QKV_SCATTER) {
                    const int which = ncol / CDIM;
                    const int rem   = ncol - which * CDIM;
                    const int h = rem >> 6, d = rem & 63;
                    float* dst = (which == 0) ? g_Q : (which == 1) ? g_K : g_V;
                    const float sc = (which == 0) ? 0.125f : 1.0f;
                    const int b_ = mrow >> 10, s_ = mrow & 1023;
                    const size_t base =
                        ((size_t)(b_ * NHEADS + h) * SEQ + s_) * HD + d;
                    dst[base]      = __uint_as_float(f2tf(v0 * sc));
                    dst[base + HD] = __uint_as_float(f2tf(v1 * sc));
                } else {
                    out[(size_t)mrow * CDIM + ncol]       = v0;
                    out[(size_t)(mrow + 1) * CDIM + ncol] = v1;
                }
            }
        }
    }
}

// ===========================================================================
// relative-position bias tables. Q is stored pre-scaled by 1/8 (tf32), so
// multiply the accumulated dot by 8 (exact) to recover unscaled bias.
// ===========================================================================
__global__ void __launch_bounds__(256) rel_kernel(
    const float* __restrict__ rph, const float* __restrict__ rpw)
{
    __shared__ float Qs[32 * 65];
    __shared__ float Hs[32 * 65];
    __shared__ float Wt[63 * 65];

    const int bh = blockIdx.y;
    const int qh = blockIdx.x;
    const int t  = threadIdx.x;

    const float* Qg = g_Q + ((size_t)bh * SEQ + qh * 32) * HD;
#pragma unroll
    for (int i = t; i < 2048; i += 256) {
        const int r = i >> 6, d = i & 63;
        Qs[r * 65 + d] = Qg[i];
        Hs[r * 65 + d] = __ldg(rph + (qh + r) * 64 + d);
    }
    for (int i = t; i < 4032; i += 256) {
        const int r = i >> 6, d = i & 63;
        Wt[r * 65 + d] = __ldg(rpw + i);
    }
    __syncthreads();

    const int w = t >> 5, lane = t & 31;
    const float* Qr = Qs + lane * 65;
    float acc[8] = {};

    if (w < 4) {
        const int baserow = 31 - w * 8;
#pragma unroll
        for (int d = 0; d < 64; d++) {
            const float qv = Qr[d];
#pragma unroll
            for (int j = 0; j < 8; j++)
                acc[j] = fmaf(qv, Hs[(baserow - j) * 65 + d], acc[j]);
        }
        float* out = g_RH + ((size_t)bh * SEQ + qh * 32 + lane) * HH + w * 8;
        *(float4*)out       = make_float4(acc[0]*8.f, acc[1]*8.f, acc[2]*8.f, acc[3]*8.f);
        *(float4*)(out + 4) = make_float4(acc[4]*8.f, acc[5]*8.f, acc[6]*8.f, acc[7]*8.f);
    } else {
        const int baserow = lane + 31 - (w - 4) * 8;
#pragma unroll
        for (int d = 0; d < 64; d++) {
            const float qv = Qr[d];
#pragma unroll
            for (int j = 0; j < 8; j++)
                acc[j] = fmaf(qv, Wt[(baserow - j) * 65 + d], acc[j]);
        }
        float* out = g_RW + ((size_t)bh * SEQ + qh * 32 + lane) * WWID
                     + (w - 4) * 8;
        *(float4*)out       = make_float4(acc[0]*8.f, acc[1]*8.f, acc[2]*8.f, acc[3]*8.f);
        *(float4*)(out + 4) = make_float4(acc[4]*8.f, acc[5]*8.f, acc[6]*8.f, acc[7]*8.f);
    }
}

// ===========================================================================
// tf32 flash attention: cp.async 2-stage K/V pipeline, inputs pre-tf32.
// No per-tile conversion, ONE barrier per tile.
// ===========================================================================
__global__ void __launch_bounds__(128, 3) flash_tf32_kernel()
{
    extern __shared__ unsigned fsm[];   // 2 * 8960 words

    const int t = threadIdx.x, w = t >> 5, lane = t & 31;
    const int g = lane >> 2, t4 = lane & 3;
    const int bh = blockIdx.y;
    const int q0 = blockIdx.x * 64;
    const int qrow = w * 16;

    const unsigned* Kg = (const unsigned*)g_K + (size_t)bh * SEQ * HD;
    const unsigned* Vg = (const unsigned*)g_V + (size_t)bh * SEQ * HD;

    const int cr = t >> 4;
    const int cc = (t & 15) * 4;

    auto fissue = [&](int kt_, int s_) {
        unsigned* Kst = fsm + s_ * 8960;
        unsigned* Vst = Kst + 4352;
#pragma unroll
        for (int i = 0; i < 8; i++) {
            const int r = cr + 8 * i;
            CP16(s2u(Kst + r * 68 + cc),
                 Kg + (size_t)(kt_ * 64 + r) * HD + cc);
            CP16(s2u(Vst + r * 72 + cc),
                 Vg + (size_t)(kt_ * 64 + r) * HD + cc);
        }
        CPCOMMIT();
    };

    // ---- stage Q (already scaled tf32) through stage-0 K area -------------
    {
        const unsigned* Qg = (const unsigned*)g_Q + ((size_t)bh * SEQ + q0) * HD;
#pragma unroll
        for (int i = 0; i < 8; i++) {
            const int r = cr + 8 * i;
            *(uint4*)&fsm[r * 68 + cc] = *(const uint4*)(Qg + r * HD + cc);
        }
        __syncthreads();
    }
    unsigned qa[8][4];
#pragma unroll
    for (int ks = 0; ks < 8; ks++) {
        const int kk = ks * 8 + t4;
        qa[ks][0] = fsm[(qrow + g) * 68 + kk];
        qa[ks][1] = fsm[(qrow + g + 8) * 68 + kk];
        qa[ks][2] = fsm[(qrow + g) * 68 + kk + 4];
        qa[ks][3] = fsm[(qrow + g + 8) * 68 + kk + 4];
    }
    __syncthreads();   // all Q frags read before tile 0 overwrites stage 0

    const float* RWg = g_RW + ((size_t)bh * SEQ + q0) * 32;
    float rwA[4][2], rwB[4][2];
#pragma unroll
    for (int nb = 0; nb < 4; nb++) {
        rwA[nb][0] = __ldg(RWg + (qrow + g) * 32 + nb * 8 + 2 * t4);
        rwA[nb][1] = __ldg(RWg + (qrow + g) * 32 + nb * 8 + 2 * t4 + 1);
        rwB[nb][0] = __ldg(RWg + (qrow + g + 8) * 32 + nb * 8 + 2 * t4);
        rwB[nb][1] = __ldg(RWg + (qrow + g + 8) * 32 + nb * 8 + 2 * t4 + 1);
    }
    const float* RHg = g_RH + ((size_t)bh * SEQ + q0) * 32;

    float o[8][4] = {};
    float l0 = 0.f, l1 = 0.f;
    const unsigned quadbase = lane & ~3u;
    const unsigned srcA = quadbase | (t4 >> 1);

    fissue(0, 0);

    for (int kt = 0; kt < 16; kt++) {
        const int s = kt & 1;
        unsigned* Kst = fsm + s * 8960;
        unsigned* Vst = Kst + 4352;

        CPWAIT(0);
        __syncthreads();
        if (kt + 1 < 16) fissue(kt + 1, s ^ 1);

        // ---- S = Q @ K^T --------------------------------------------------
        float sreg[8][4] = {};
#pragma unroll
        for (int ks = 0; ks < 8; ks++) {
            const int kk = ks * 8 + t4;
#pragma unroll
            for (int nt = 0; nt < 8; nt++) {
                unsigned b[2];
                b[0] = Kst[(nt * 8 + g) * 68 + kk];
                b[1] = Kst[(nt * 8 + g) * 68 + kk + 4];
                mma_tf32(sreg[nt], qa[ks], b);
            }
        }

        // ---- bias + exp + frag convert + O += P @ V -----------------------
        const float rhA0 = __ldg(RHg + (qrow + g) * 32 + kt * 2);
        const float rhA1 = __ldg(RHg + (qrow + g) * 32 + kt * 2 + 1);
        const float rhB0 = __ldg(RHg + (qrow + g + 8) * 32 + kt * 2);
        const float rhB1 = __ldg(RHg + (qrow + g + 8) * 32 + kt * 2 + 1);
#pragma unroll
        for (int nt = 0; nt < 8; nt++) {
            const float bA = (nt < 4) ? rhA0 : rhA1;
            const float bB = (nt < 4) ? rhB0 : rhB1;
            const int n4 = nt & 3;
            const float p00 = __expf(fminf(sreg[nt][0] + bA + rwA[n4][0], 60.f));
            const float p01 = __expf(fminf(sreg[nt][1] + bA + rwA[n4][1], 60.f));
            const float p10 = __expf(fminf(sreg[nt][2] + bB + rwB[n4][0], 60.f));
            const float p11 = __expf(fminf(sreg[nt][3] + bB + rwB[n4][1], 60.f));
            l0 += p00 + p01;
            l1 += p10 + p11;

            const bool oddsel = (t4 & 1);
            float xa, xb, ya, yb;
            xa = __shfl_sync(0xffffffffu, p00, srcA);
            xb = __shfl_sync(0xffffffffu, p01, srcA);
            const float loA = oddsel ? xb : xa;
            ya = __shfl_sync(0xffffffffu, p00, srcA + 2);
            yb = __shfl_sync(0xffffffffu, p01, srcA + 2);
            const float hiA = oddsel ? yb : ya;
            xa = __shfl_sync(0xffffffffu, p10, srcA);
            xb = __shfl_sync(0xffffffffu, p11, srcA);
            const float loB = oddsel ? xb : xa;
            ya = __shfl_sync(0xffffffffu, p10, srcA + 2);
            yb = __shfl_sync(0xffffffffu, p11, srcA + 2);
            const float hiB = oddsel ? yb : ya;

            unsigned ap[4];
            ap[0] = f2tf(loA);
            ap[1] = f2tf(loB);
            ap[2] = f2tf(hiA);
            ap[3] = f2tf(hiB);

            const int kc = nt * 8;
#pragma unroll
            for (int db = 0; db < 8; db++) {
                unsigned b[2];
                b[0] = Vst[(kc + t4) * 72 + db * 8 + g];
                b[1] = Vst[(kc + t4 + 4) * 72 + db * 8 + g];
                mma_tf32(o[db], ap, b);
            }
        }
    }

    l0 += __shfl_xor_sync(0xffffffffu, l0, 1);
    l0 += __shfl_xor_sync(0xffffffffu, l0, 2);
    l1 += __shfl_xor_sync(0xffffffffu, l1, 1);
    l1 += __shfl_xor_sync(0xffffffffu, l1, 2);
    const float inv0 = 1.f / l0;
    const float inv1 = 1.f / l1;

    const int b_ = bh / NHEADS, h = bh - b_ * NHEADS;
    const int rowA = q0 + qrow + g, rowB = rowA + 8;
    unsigned* OgA = g_ATT + ((size_t)b_ * SEQ + rowA) * CDIM + h * HD;
    unsigned* OgB = g_ATT + ((size_t)b_ * SEQ + rowB) * CDIM + h * HD;
#pragma unroll
    for (int db = 0; db < 8; db++) {
        const int c = db * 8 + 2 * t4;
        uint2 vA = make_uint2(f2tf(o[db][0] * inv0), f2tf(o[db][1] * inv0));
        uint2 vB = make_uint2(f2tf(o[db][2] * inv1), f2tf(o[db][3] * inv1));
        *(uint2*)(OgA + c) = vA;
        *(uint2*)(OgB + c) = vB;
    }
}

// ===========================================================================
// launch
// ===========================================================================
#define GEMM_SMEM (2 * 8960 * 4)
#define FLASH_SMEM (2 * 8960 * 4)

extern "C" void kernel_launch(void* const* d_in, const int* in_sizes, int n_in,
                              void* d_out, int out_size)
{
    const float* hidden = (const float*)d_in[0];
    const float* qkv_w  = (const float*)d_in[1];
    const float* qkv_b  = (const float*)d_in[2];
    const float* proj_w = (const float*)d_in[3];
    const float* proj_b = (const float*)d_in[4];
    const float* rph    = (const float*)d_in[5];
    const float* rpw    = (const float*)d_in[6];
    float* out = (float*)d_out;

    static bool init = false;
    if (!init) {
        cudaFuncSetAttribute(gemm_tf32_kernel<N_QKV, true>,
                             cudaFuncAttributeMaxDynamicSharedMemorySize,
                             GEMM_SMEM);
        cudaFuncSetAttribute(gemm_tf32_kernel<CDIM, false>,
                             cudaFuncAttributeMaxDynamicSharedMemorySize,
                             GEMM_SMEM);
        cudaFuncSetAttribute(flash_tf32_kernel,
                             cudaFuncAttributeMaxDynamicSharedMemorySize,
                             FLASH_SMEM);
        init = true;
    }

    unsigned *x_ptr = nullptr, *w1_ptr = nullptr, *w2_ptr = nullptr,
             *att_ptr = nullptr;
    cudaGetSymbolAddress((void**)&x_ptr,  g_X);
    cudaGetSymbolAddress((void**)&w1_ptr, g_W1);
    cudaGetSymbolAddress((void**)&w2_ptr, g_W2);
    cudaGetSymbolAddress((void**)&att_ptr, g_ATT);

    // pre-convert inputs to tf32
    {
        const int nX  = BATCH * SEQ * CDIM / 4;      // 1572864
        const int nW1 = CDIM * N_QKV / 4;            // 442368
        const int nW2 = CDIM * CDIM / 4;             // 147456
        cvt_kernel<<<(nX  + 255) / 256, 256>>>((const float4*)hidden,
                                               (uint4*)x_ptr,  nX);
        cvt_kernel<<<(nW1 + 255) / 256, 256>>>((const float4*)qkv_w,
                                               (uint4*)w1_ptr, nW1);
        cvt_kernel<<<(nW2 + 255) / 256, 256>>>((const float4*)proj_w,
                                               (uint4*)w2_ptr, nW2);
    }

    gemm_tf32_kernel<N_QKV, true>
        <<<dim3(N_QKV / 128, (BATCH * SEQ) / 128), 256, GEMM_SMEM>>>(
            x_ptr, w1_ptr, qkv_b, nullptr);
    rel_kernel<<<dim3(HH, BHEADS), 256>>>(rph, rpw);
    flash_tf32_kernel<<<dim3(SEQ / 64, BHEADS), 128, FLASH_SMEM>>>();
    gemm_tf32_kernel<CDIM, false>
        <<<dim3(CDIM / 128, (BATCH * SEQ) / 128), 256, GEMM_SMEM>>>(
            att_ptr, w2_ptr, proj_b, out);
}

// round 12
// speedup vs baseline: 1.9176x; 1.4949x over previous
#include <cuda_runtime.h>
#include <cuda_fp16.h>

// ---- static problem shape -------------------------------------------------
#define BATCH   8
#define HH      32
#define WWID    32
#define CDIM    768
#define NHEADS  12
#define HD      64
#define SEQ     1024
#define BHEADS  96
#define N_QKV   2304

// ---- scratch (device globals; allocation is forbidden) ---------------------
__device__ __align__(256) __half g_Q  [(size_t)BHEADS * SEQ * HD];   // pre-scaled 1/8
__device__ __align__(256) __half g_K  [(size_t)BHEADS * SEQ * HD];
__device__ __align__(256) __half g_Vt [(size_t)BHEADS * HD * SEQ];   // [bh][d][s]
__device__ __align__(256) float  g_RH [(size_t)BHEADS * SEQ * HH];
__device__ __align__(256) float  g_RW [(size_t)BHEADS * SEQ * WWID];
__device__ __align__(256) __half g_ATT[(size_t)BATCH * SEQ * CDIM];
__device__ __align__(256) __half g_X  [(size_t)BATCH * SEQ * CDIM];
__device__ __align__(256) __half g_W1t[(size_t)N_QKV * CDIM];        // [n][k]
__device__ __align__(256) __half g_W2t[(size_t)CDIM * CDIM];         // [n][k]

// ---- helpers ---------------------------------------------------------------
__device__ __forceinline__ unsigned pack_half2(float lo, float hi) {
    unsigned r;
    asm("cvt.rn.f16x2.f32 %0, %1, %2;" : "=r"(r) : "f"(hi), "f"(lo));
    return r;
}
__device__ __forceinline__ void mma_f16(float c[4], const unsigned a[4],
                                        const unsigned b[2]) {
    asm volatile(
        "mma.sync.aligned.m16n8k16.row.col.f32.f16.f16.f32 "
        "{%0,%1,%2,%3},{%4,%5,%6,%7},{%8,%9},{%0,%1,%2,%3};"
        : "+f"(c[0]), "+f"(c[1]), "+f"(c[2]), "+f"(c[3])
        : "r"(a[0]), "r"(a[1]), "r"(a[2]), "r"(a[3]), "r"(b[0]), "r"(b[1]));
}

// ===========================================================================
// Pre-pass 1: fp32 -> fp16 elementwise (hidden).
// ===========================================================================
__global__ void __launch_bounds__(256) cvt_kernel(
    const float4* __restrict__ src, uint2* __restrict__ dst, int n4)
{
    const int i = blockIdx.x * 256 + threadIdx.x;
    if (i < n4) {
        float4 v = src[i];
        dst[i] = make_uint2(pack_half2(v.x, v.y), pack_half2(v.z, v.w));
    }
}

// ===========================================================================
// Pre-pass 2: transpose + convert weights.  Wt[n][k] = fp16(W[k][n]).
// ===========================================================================
__global__ void __launch_bounds__(256) transpose_cvt_kernel(
    const float* __restrict__ W, __half* __restrict__ Wt, int K, int N)
{
    __shared__ float tile[32][33];
    const int n0 = blockIdx.x * 32, k0 = blockIdx.y * 32;
    const int tx = threadIdx.x & 31, ty = threadIdx.x >> 5;
#pragma unroll
    for (int r = 0; r < 32; r += 8)
        tile[ty + r][tx] = W[(size_t)(k0 + ty + r) * N + n0 + tx];
    __syncthreads();
#pragma unroll
    for (int r = 0; r < 32; r += 8)
        Wt[(size_t)(n0 + ty + r) * K + k0 + tx] = __float2half(tile[tx][ty + r]);
}

// ===========================================================================
// fp16 GEMM:  out(8192 x N) = X @ W + bias, computed transposed
// (D = W^T @ X^T).  Block 128N x 128M, k-step 64, synchronous copies.
// Tiles row-major [row][k-words], stride 36 words.  Static smem 36 KB.
// ===========================================================================
template<bool QKV_SCATTER>
__global__ void __launch_bounds__(256, 2) gemm_f16_kernel(
    const __half* __restrict__ X, const __half* __restrict__ Wt,
    const float* __restrict__ bias, float* __restrict__ out)
{
    __shared__ unsigned Wsm[128 * 36];
    __shared__ unsigned Xsm[128 * 36];

    const int t = threadIdx.x;
    const int w = t >> 5, lane = t & 31, g = lane >> 2, t4 = lane & 3;
    const int warpN = (w & 3) * 32, warpM = (w >> 2) * 64;
    const int bn = blockIdx.x * 128, bm = blockIdx.y * 128;

    float acc[2][8][4] = {};

    for (int i = 0; i < 12; i++) {
        uint4 wreg[4], xreg[4];
#pragma unroll
        for (int j = 0; j < 4; j++) {
            const int idx = t + 256 * j;
            const int row = idx >> 3, u4 = idx & 7;
            wreg[j] = *(const uint4*)(Wt + (size_t)(bn + row) * CDIM
                                      + i * 64 + u4 * 8);
            xreg[j] = *(const uint4*)(X + (size_t)(bm + row) * CDIM
                                      + i * 64 + u4 * 8);
        }
        __syncthreads();
#pragma unroll
        for (int j = 0; j < 4; j++) {
            const int idx = t + 256 * j;
            const int row = idx >> 3, u4 = idx & 7;
            *(uint4*)&Wsm[row * 36 + u4 * 4] = wreg[j];
            *(uint4*)&Xsm[row * 36 + u4 * 4] = xreg[j];
        }
        __syncthreads();

#pragma unroll
        for (int ks = 0; ks < 4; ks++) {
            const int kw = ks * 8;
            unsigned a[2][4];
#pragma unroll
            for (int mt = 0; mt < 2; mt++) {
                const int nr = warpN + mt * 16 + g;
                a[mt][0] = Wsm[nr * 36 + kw + t4];
                a[mt][1] = Wsm[(nr + 8) * 36 + kw + t4];
                a[mt][2] = Wsm[nr * 36 + kw + t4 + 4];
                a[mt][3] = Wsm[(nr + 8) * 36 + kw + t4 + 4];
            }
#pragma unroll
            for (int nt = 0; nt < 8; nt++) {
                unsigned b[2];
                const int mr = (warpM + nt * 8 + g) * 36 + kw;
                b[0] = Xsm[mr + t4];
                b[1] = Xsm[mr + t4 + 4];
                mma_f16(acc[0][nt], a[0], b);
                mma_f16(acc[1][nt], a[1], b);
            }
        }
    }

#pragma unroll
    for (int mt = 0; mt < 2; mt++) {
#pragma unroll
        for (int nt = 0; nt < 8; nt++) {
            const int ncol0 = bn + warpN + mt * 16 + g;
            const int mrow  = bm + warpM + nt * 8 + 2 * t4;
#pragma unroll
            for (int h8 = 0; h8 < 2; h8++) {
                const int ncol = ncol0 + h8 * 8;
                const float bs = __ldg(bias + ncol);
                const float v0 = acc[mt][nt][h8 * 2 + 0] + bs;
                const float v1 = acc[mt][nt][h8 * 2 + 1] + bs;
                if (QKV_SCATTER) {
                    const int which = ncol / CDIM;
                    const int rem   = ncol - which * CDIM;
                    const int h = rem >> 6, d = rem & 63;
                    const int b_ = mrow >> 10, s_ = mrow & 1023;
                    const int bh = b_ * NHEADS + h;
                    if (which == 2) {
                        __half* vp = g_Vt + ((size_t)bh * HD + d) * SEQ + s_;
                        vp[0] = __float2half(v0);
                        vp[1] = __float2half(v1);
                    } else {
                        __half* dst = (which == 0) ? g_Q : g_K;
                        const float sc = (which == 0) ? 0.125f : 1.0f;
                        const size_t base =
                            ((size_t)bh * SEQ + s_) * HD + d;
                        dst[base]      = __float2half(v0 * sc);
                        dst[base + HD] = __float2half(v1 * sc);
                    }
                } else {
                    out[(size_t)mrow * CDIM + ncol]       = v0;
                    out[(size_t)(mrow + 1) * CDIM + ncol] = v1;
                }
            }
        }
    }
}

// ===========================================================================
// relative-position bias (Q fp16, pre-scaled 1/8 -> output x8).
// ===========================================================================
__global__ void __launch_bounds__(256) rel_kernel(
    const float* __restrict__ rph, const float* __restrict__ rpw)
{
    __shared__ float Qs[32 * 65];
    __shared__ float Hs[32 * 65];
    __shared__ float Wt[63 * 65];

    const int bh = blockIdx.y;
    const int qh = blockIdx.x;
    const int t  = threadIdx.x;

    const __half* Qg = g_Q + ((size_t)bh * SEQ + qh * 32) * HD;
#pragma unroll
    for (int i = t; i < 2048; i += 256) {
        const int r = i >> 6, d = i & 63;
        Qs[r * 65 + d] = __half2float(Qg[i]);
        Hs[r * 65 + d] = __ldg(rph + (qh + r) * 64 + d);
    }
    for (int i = t; i < 4032; i += 256) {
        const int r = i >> 6, d = i & 63;
        Wt[r * 65 + d] = __ldg(rpw + i);
    }
    __syncthreads();

    const int w = t >> 5, lane = t & 31;
    const float* Qr = Qs + lane * 65;
    float acc[8] = {};

    if (w < 4) {
        const int baserow = 31 - w * 8;
#pragma unroll
        for (int d = 0; d < 64; d++) {
            const float qv = Qr[d];
#pragma unroll
            for (int j = 0; j < 8; j++)
                acc[j] = fmaf(qv, Hs[(baserow - j) * 65 + d], acc[j]);
        }
        float* out = g_RH + ((size_t)bh * SEQ + qh * 32 + lane) * HH + w * 8;
        *(float4*)out       = make_float4(acc[0]*8.f, acc[1]*8.f, acc[2]*8.f, acc[3]*8.f);
        *(float4*)(out + 4) = make_float4(acc[4]*8.f, acc[5]*8.f, acc[6]*8.f, acc[7]*8.f);
    } else {
        const int baserow = lane + 31 - (w - 4) * 8;
#pragma unroll
        for (int d = 0; d < 64; d++) {
            const float qv = Qr[d];
#pragma unroll
            for (int j = 0; j < 8; j++)
                acc[j] = fmaf(qv, Wt[(baserow - j) * 65 + d], acc[j]);
        }
        float* out = g_RW + ((size_t)bh * SEQ + qh * 32 + lane) * WWID
                     + (w - 4) * 8;
        *(float4*)out       = make_float4(acc[0]*8.f, acc[1]*8.f, acc[2]*8.f, acc[3]*8.f);
        *(float4*)(out + 4) = make_float4(acc[4]*8.f, acc[5]*8.f, acc[6]*8.f, acc[7]*8.f);
    }
}

// ===========================================================================
// fp16 flash attention.  Block = 64 queries (4 warps x 16), key tiles of 64.
// S = Q@K^T via m16n8k16; softmaxed S packs DIRECTLY into PV A-fragments.
// V consumed transposed (g_Vt).  Synchronous tile copies.  Static smem 18 KB.
// rw bias: key = nt*8 + 2*t4, rw index = key & 31 = (nt&3)*8 + 2*t4  (the
// round-9..11 rwA[nt] indexing read past g_RW's end -> the IMA).
// ===========================================================================
__global__ void __launch_bounds__(128, 3) flash_f16_kernel()
{
    __shared__ unsigned Ks[64 * 36];
    __shared__ unsigned Vs[64 * 36];

    const int t = threadIdx.x, w = t >> 5, lane = t & 31;
    const int g = lane >> 2, t4 = lane & 3;
    const int bh = blockIdx.y;
    const int q0 = blockIdx.x * 64;
    const int qrow = w * 16;

    const __half* Kg  = g_K  + (size_t)bh * SEQ * HD;
    const __half* Vtg = g_Vt + (size_t)bh * HD * SEQ;

    // ---- stage Q tile into Ks, pull fragments ------------------------------
    {
        const __half* Qg = g_Q + ((size_t)bh * SEQ + q0) * HD;
#pragma unroll
        for (int j = 0; j < 4; j++) {
            const int idx = t + 128 * j;
            const int row = idx >> 3, u4 = idx & 7;
            *(uint4*)&Ks[row * 36 + u4 * 4] =
                *(const uint4*)(Qg + (size_t)row * HD + u4 * 8);
        }
        __syncthreads();
    }
    unsigned qa[4][4];
#pragma unroll
    for (int c = 0; c < 4; c++) {
        const int kw = c * 8;
        qa[c][0] = Ks[(qrow + g) * 36 + kw + t4];
        qa[c][1] = Ks[(qrow + g + 8) * 36 + kw + t4];
        qa[c][2] = Ks[(qrow + g) * 36 + kw + t4 + 4];
        qa[c][3] = Ks[(qrow + g + 8) * 36 + kw + t4 + 4];
    }
    __syncthreads();   // all Q frags read before tile 0 overwrites Ks

    // ---- rw bias (tile-invariant, 32-wide) into registers ------------------
    const float* RWg = g_RW + ((size_t)bh * SEQ + q0) * 32;
    float rwA[4][2], rwB[4][2];
#pragma unroll
    for (int nb = 0; nb < 4; nb++) {
        rwA[nb][0] = __ldg(RWg + (qrow + g) * 32 + nb * 8 + 2 * t4);
        rwA[nb][1] = __ldg(RWg + (qrow + g) * 32 + nb * 8 + 2 * t4 + 1);
        rwB[nb][0] = __ldg(RWg + (qrow + g + 8) * 32 + nb * 8 + 2 * t4);
        rwB[nb][1] = __ldg(RWg + (qrow + g + 8) * 32 + nb * 8 + 2 * t4 + 1);
    }
    const float* RHg = g_RH + ((size_t)bh * SEQ + q0) * 32;

    float o[8][4] = {};
    float l0 = 0.f, l1 = 0.f;

    for (int kt = 0; kt < 16; kt++) {
        uint4 kreg[4], vreg[4];
#pragma unroll
        for (int j = 0; j < 4; j++) {
            const int idx = t + 128 * j;
            const int row = idx >> 3, u4 = idx & 7;
            kreg[j] = *(const uint4*)(Kg + (size_t)(kt * 64 + row) * HD
                                      + u4 * 8);
            vreg[j] = *(const uint4*)(Vtg + (size_t)row * SEQ + kt * 64
                                      + u4 * 8);
        }
        __syncthreads();
#pragma unroll
        for (int j = 0; j < 4; j++) {
            const int idx = t + 128 * j;
            const int row = idx >> 3, u4 = idx & 7;
            *(uint4*)&Ks[row * 36 + u4 * 4] = kreg[j];
            *(uint4*)&Vs[row * 36 + u4 * 4] = vreg[j];
        }
        __syncthreads();

        // ---- S = Q @ K^T ----------------------------------------------------
        float sreg[8][4] = {};
#pragma unroll
        for (int c = 0; c < 4; c++) {
            const int kw = c * 8;
#pragma unroll
            for (int nt = 0; nt < 8; nt++) {
                unsigned b[2];
                const int kr = (nt * 8 + g) * 36 + kw;
                b[0] = Ks[kr + t4];
                b[1] = Ks[kr + t4 + 4];
                mma_f16(sreg[nt], qa[c], b);
            }
        }

        // ---- softmax -> packed P fragments ----------------------------------
        const float rhA0 = __ldg(RHg + (qrow + g) * 32 + kt * 2);
        const float rhA1 = __ldg(RHg + (qrow + g) * 32 + kt * 2 + 1);
        const float rhB0 = __ldg(RHg + (qrow + g + 8) * 32 + kt * 2);
        const float rhB1 = __ldg(RHg + (qrow + g + 8) * 32 + kt * 2 + 1);
        unsigned pk[8][2];
#pragma unroll
        for (int nt = 0; nt < 8; nt++) {
            const float bA = (nt < 4) ? rhA0 : rhA1;
            const float bB = (nt < 4) ? rhB0 : rhB1;
            const int n4 = nt & 3;   // key&31 = (nt&3)*8 + 2*t4
            const float p00 = __expf(fminf(sreg[nt][0] + bA + rwA[n4][0], 60.f));
            const float p01 = __expf(fminf(sreg[nt][1] + bA + rwA[n4][1], 60.f));
            const float p10 = __expf(fminf(sreg[nt][2] + bB + rwB[n4][0], 60.f));
            const float p11 = __expf(fminf(sreg[nt][3] + bB + rwB[n4][1], 60.f));
            l0 += p00 + p01;
            l1 += p10 + p11;
            pk[nt][0] = pack_half2(p00, p01);
            pk[nt][1] = pack_half2(p10, p11);
        }

        // ---- O += P @ V -----------------------------------------------------
#pragma unroll
        for (int kv = 0; kv < 4; kv++) {
            unsigned ap[4];
            ap[0] = pk[2 * kv][0];
            ap[1] = pk[2 * kv][1];
            ap[2] = pk[2 * kv + 1][0];
            ap[3] = pk[2 * kv + 1][1];
            const int kw = kv * 8;
#pragma unroll
            for (int db = 0; db < 8; db++) {
                unsigned b[2];
                const int vr = (db * 8 + g) * 36 + kw;
                b[0] = Vs[vr + t4];
                b[1] = Vs[vr + t4 + 4];
                mma_f16(o[db], ap, b);
            }
        }
    }

    // ---- finalize -----------------------------------------------------------
    l0 += __shfl_xor_sync(0xffffffffu, l0, 1);
    l0 += __shfl_xor_sync(0xffffffffu, l0, 2);
    l1 += __shfl_xor_sync(0xffffffffu, l1, 1);
    l1 += __shfl_xor_sync(0xffffffffu, l1, 2);
    const float inv0 = 1.f / l0;
    const float inv1 = 1.f / l1;

    const int b_ = bh / NHEADS, h = bh - b_ * NHEADS;
    const int rowA = q0 + qrow + g, rowB = rowA + 8;
    __half* OgA = g_ATT + ((size_t)b_ * SEQ + rowA) * CDIM + h * HD;
    __half* OgB = g_ATT + ((size_t)b_ * SEQ + rowB) * CDIM + h * HD;
#pragma unroll
    for (int db = 0; db < 8; db++) {
        const int c = db * 8 + 2 * t4;
        OgA[c]     = __float2half(o[db][0] * inv0);
        OgA[c + 1] = __float2half(o[db][1] * inv0);
        OgB[c]     = __float2half(o[db][2] * inv1);
        OgB[c + 1] = __float2half(o[db][3] * inv1);
    }
}

// ===========================================================================
// launch
// ===========================================================================
extern "C" void kernel_launch(void* const* d_in, const int* in_sizes, int n_in,
                              void* d_out, int out_size)
{
    const float* hidden = (const float*)d_in[0];
    const float* qkv_w  = (const float*)d_in[1];
    const float* qkv_b  = (const float*)d_in[2];
    const float* proj_w = (const float*)d_in[3];
    const float* proj_b = (const float*)d_in[4];
    const float* rph    = (const float*)d_in[5];
    const float* rpw    = (const float*)d_in[6];
    float* out = (float*)d_out;

    __half *x_ptr = nullptr, *w1t_ptr = nullptr, *w2t_ptr = nullptr,
           *att_ptr = nullptr;
    cudaGetSymbolAddress((void**)&x_ptr,   g_X);
    cudaGetSymbolAddress((void**)&w1t_ptr, g_W1t);
    cudaGetSymbolAddress((void**)&w2t_ptr, g_W2t);
    cudaGetSymbolAddress((void**)&att_ptr, g_ATT);

    // pre-convert hidden; transpose+convert weights
    {
        const int nX = BATCH * SEQ * CDIM / 4;
        cvt_kernel<<<(nX + 255) / 256, 256>>>((const float4*)hidden,
                                              (uint2*)x_ptr, nX);
        transpose_cvt_kernel<<<dim3(N_QKV / 32, CDIM / 32), 256>>>(
            qkv_w, w1t_ptr, CDIM, N_QKV);
        transpose_cvt_kernel<<<dim3(CDIM / 32, CDIM / 32), 256>>>(
            proj_w, w2t_ptr, CDIM, CDIM);
    }

    gemm_f16_kernel<true>
        <<<dim3(N_QKV / 128, (BATCH * SEQ) / 128), 256>>>(
            x_ptr, w1t_ptr, qkv_b, nullptr);
    rel_kernel<<<dim3(HH, BHEADS), 256>>>(rph, rpw);
    flash_f16_kernel<<<dim3(SEQ / 64, BHEADS), 128>>>();
    gemm_f16_kernel<false>
        <<<dim3(CDIM / 128, (BATCH * SEQ) / 128), 256>>>(
            att_ptr, w2t_ptr, proj_b, out);
}